// round 3
// baseline (speedup 1.0000x reference)
#include <cuda_runtime.h>
#include <cuda_bf16.h>
#include <cstdint>
#include <cstddef>

#define TT 512
#define BB 64
#define NCTA 64

// ---------------- static scratch ----------------
__device__ float g_seqA[(size_t)TT * BB * 512];   // layer-output sequence (T,B,H) ping
__device__ float g_seqB[(size_t)TT * BB * 512];   // pong
__device__ float g_G[(size_t)TT * BB * 2048];     // precomputed input gates (T*B, 4H)
__device__ float g_hbuf[2][BB * 512];             // double-buffered recurrent h
__device__ float g_hT[BB * 512];                  // encoder final h
__device__ float g_cT[BB * 512];                  // encoder final c
__device__ int g_barCount;
__device__ volatile int g_barGen;

// ---------------- helpers ----------------
__device__ __forceinline__ uint32_t f2tf32(float f) {
    uint32_t u;
    asm("cvt.rna.tf32.f32 %0, %1;" : "=r"(u) : "f"(f));
    return u;
}

__device__ __forceinline__ void mma_tf32(float c[4], uint32_t a0, uint32_t a1,
                                         uint32_t a2, uint32_t a3,
                                         uint32_t b0, uint32_t b1) {
    asm volatile(
        "mma.sync.aligned.m16n8k8.row.col.f32.tf32.tf32.f32 "
        "{%0,%1,%2,%3}, {%4,%5,%6,%7}, {%8,%9}, {%0,%1,%2,%3};"
        : "+f"(c[0]), "+f"(c[1]), "+f"(c[2]), "+f"(c[3])
        : "r"(a0), "r"(a1), "r"(a2), "r"(a3), "r"(b0), "r"(b1));
}

__device__ __forceinline__ float sigf(float x) { return 1.0f / (1.0f + __expf(-x)); }

__device__ __forceinline__ void grid_sync() {
    __threadfence();
    __syncthreads();
    if (threadIdx.x == 0) {
        int g = g_barGen;
        if (atomicAdd(&g_barCount, 1) == NCTA - 1) {
            g_barCount = 0;
            __threadfence();
            g_barGen = g + 1;
        } else {
            while (g_barGen == g) { __nanosleep(32); }
        }
        __threadfence();
    }
    __syncthreads();
}

// ---------------- input GEMM: G = src @ W^T + b1 + b2 --------------------------
// M = T*B = 32768 (row m = t*64 + b), N = 4H, K = in_dim. 128x128x32 tiles, tf32.
// srcSel: 0 = raw x in (B,T,I) layout (rev reverses time), 1/2 = seqA/B (T,B,H).
__global__ void __launch_bounds__(256) gemm_input(int srcSel,
                                                  const float* __restrict__ xin,
                                                  const float* __restrict__ W,
                                                  const float* __restrict__ b1,
                                                  const float* __restrict__ b2,
                                                  int Kdim, int Ndim, int rev) {
    __shared__ __align__(16) uint32_t As[128][36];
    __shared__ __align__(16) uint32_t Bs[128][36];

    const float* __restrict__ S = (srcSel == 0) ? xin : (srcSel == 1) ? g_seqA : g_seqB;

    int tid = threadIdx.x;
    int wid = tid >> 5, lane = tid & 31, l4 = lane >> 2, tig = lane & 3;
    int wr = wid >> 2, wc = wid & 3;                 // warp grid 2 x 4 (64x32 tiles)
    int m0 = blockIdx.y * 128, n0 = blockIdx.x * 128;

    float acc[4][4][4];
#pragma unroll
    for (int fm = 0; fm < 4; fm++)
#pragma unroll
        for (int fn = 0; fn < 4; fn++)
#pragma unroll
            for (int i = 0; i < 4; i++) acc[fm][fn][i] = 0.0f;

    for (int kt = 0; kt < Kdim; kt += 32) {
#pragma unroll
        for (int i = 0; i < 4; i++) {
            int v = tid + i * 256;
            int row = v >> 3, kv = v & 7;
            int m = m0 + row;
            size_t off;
            if (srcSel == 0) {
                int t = m >> 6;
                if (rev) t = TT - 1 - t;
                off = ((size_t)(m & 63) * TT + t) * Kdim;
            } else {
                off = (size_t)m * Kdim;
            }
            float4 a4 = *(const float4*)(S + off + kt + kv * 4);
            uint4 ua;
            ua.x = f2tf32(a4.x); ua.y = f2tf32(a4.y);
            ua.z = f2tf32(a4.z); ua.w = f2tf32(a4.w);
            *(uint4*)&As[row][kv * 4] = ua;
            float4 b4 = *(const float4*)(W + (size_t)(n0 + row) * Kdim + kt + kv * 4);
            uint4 ub;
            ub.x = f2tf32(b4.x); ub.y = f2tf32(b4.y);
            ub.z = f2tf32(b4.z); ub.w = f2tf32(b4.w);
            *(uint4*)&Bs[row][kv * 4] = ub;
        }
        __syncthreads();

#pragma unroll
        for (int ks = 0; ks < 4; ks++) {
            const int k = ks * 8;
            uint32_t af[4][4], bf[4][2];
#pragma unroll
            for (int fm = 0; fm < 4; fm++) {
                int r = wr * 64 + fm * 16 + l4;
                af[fm][0] = As[r][k + tig];
                af[fm][1] = As[r + 8][k + tig];
                af[fm][2] = As[r][k + tig + 4];
                af[fm][3] = As[r + 8][k + tig + 4];
            }
#pragma unroll
            for (int fn = 0; fn < 4; fn++) {
                int c = wc * 32 + fn * 8 + l4;
                bf[fn][0] = Bs[c][k + tig];
                bf[fn][1] = Bs[c][k + tig + 4];
            }
#pragma unroll
            for (int fm = 0; fm < 4; fm++)
#pragma unroll
                for (int fn = 0; fn < 4; fn++)
                    mma_tf32(acc[fm][fn], af[fm][0], af[fm][1], af[fm][2], af[fm][3],
                             bf[fn][0], bf[fn][1]);
        }
        __syncthreads();
    }

#pragma unroll
    for (int fm = 0; fm < 4; fm++) {
        int r = m0 + wr * 64 + fm * 16 + l4;
#pragma unroll
        for (int fn = 0; fn < 4; fn++) {
            int c = n0 + wc * 32 + fn * 8 + 2 * tig;
            float bias0 = b1[c] + b2[c];
            float bias1 = b1[c + 1] + b2[c + 1];
            g_G[(size_t)r * Ndim + c]           = acc[fm][fn][0] + bias0;
            g_G[(size_t)r * Ndim + c + 1]       = acc[fm][fn][1] + bias1;
            g_G[(size_t)(r + 8) * Ndim + c]     = acc[fm][fn][2] + bias0;
            g_G[(size_t)(r + 8) * Ndim + c + 1] = acc[fm][fn][3] + bias1;
        }
    }
}

// ---------------- persistent recurrent LSTM pass -------------------------------
// 64 CTAs x 256 threads. CTA owns HW = H/64 hidden units (GW = 4*HW gate cols).
// Whh slice cached in SMEM (tf32). Per step: gates(64 x GW) = h(64 x H) @ Whh^T
// (+ precomputed G[t]), fused cell, grid barrier.
template <int H>
__global__ void __launch_bounds__(256) lstm_rec(const float* __restrict__ Whh,
                                                int h0FromEnc, int outSel,
                                                float* __restrict__ outFinal,
                                                int saveFinal) {
    constexpr int HW = H / 64;
    constexpr int GW = 4 * HW;
    constexpr int NF = GW / 16;       // 8-wide n-frags per warp (2 warp cols)
    constexpr int WST = H + 4;        // Whs row stride (u32)
    constexpr int NCH = H / 64;       // K chunks of 64

    extern __shared__ unsigned char smraw[];
    uint32_t* Whs = (uint32_t*)smraw;                  // GW * WST
    uint32_t* hsm = Whs + GW * WST;                    // 2 * 64 * 68
    float* gsm = (float*)(hsm + 2 * 64 * 68);          // 64 * GW
    float* csm = gsm + 64 * GW;                        // 64 * HW

    int tid = threadIdx.x, bid = blockIdx.x;
    int wid = tid >> 5, lane = tid & 31, l4 = lane >> 2, tig = lane & 3;
    int wm = wid & 3, wn = wid >> 2;
    int j0 = bid * HW;
    int cbase = wn * (GW / 2);

    float* __restrict__ Hout = (outSel == 0) ? g_seqA : (outSel == 1) ? g_seqB : outFinal;

    // cache Whh slice (tf32): local col c -> Whh row (c/HW)*H + j0 + (c%HW)
    for (int v = tid; v < GW * (H / 4); v += 256) {
        int c = v / (H / 4);
        int kv = v % (H / 4);
        int gr = (c / HW) * H + j0 + (c % HW);
        float4 w4 = *(const float4*)(Whh + (size_t)gr * H + kv * 4);
        uint4 u;
        u.x = f2tf32(w4.x); u.y = f2tf32(w4.y);
        u.z = f2tf32(w4.z); u.w = f2tf32(w4.w);
        *(uint4*)&Whs[c * WST + kv * 4] = u;
    }

    for (int e = tid; e < 64 * HW; e += 256) {
        int b = e / HW, u = e % HW;
        csm[e] = h0FromEnc ? g_cT[b * H + j0 + u] : 0.0f;
        g_hbuf[0][b * H + j0 + u] = h0FromEnc ? g_hT[b * H + j0 + u] : 0.0f;
    }
    grid_sync();

    for (int t = 0; t < TT; t++) {
        const int cur = t & 1;
        const float* __restrict__ hcur = g_hbuf[cur];

        float acc[NF][4];
#pragma unroll
        for (int fn = 0; fn < NF; fn++)
#pragma unroll
            for (int i = 0; i < 4; i++) acc[fn][i] = 0.0f;

        // preload K-chunk 0 into hsm buf 0
        {
            float4 pre[4];
#pragma unroll
            for (int i = 0; i < 4; i++) {
                int v = tid + i * 256;
                pre[i] = *(const float4*)&hcur[(v >> 4) * H + (v & 15) * 4];
            }
#pragma unroll
            for (int i = 0; i < 4; i++) {
                int v = tid + i * 256;
                uint4 u;
                u.x = f2tf32(pre[i].x); u.y = f2tf32(pre[i].y);
                u.z = f2tf32(pre[i].z); u.w = f2tf32(pre[i].w);
                *(uint4*)&hsm[(v >> 4) * 68 + (v & 15) * 4] = u;
            }
        }
        __syncthreads();

#pragma unroll
        for (int kc = 0; kc < NCH; kc++) {
            float4 nxt[4];
            if (kc + 1 < NCH) {
#pragma unroll
                for (int i = 0; i < 4; i++) {
                    int v = tid + i * 256;
                    nxt[i] = *(const float4*)&hcur[(v >> 4) * H + (kc + 1) * 64 + (v & 15) * 4];
                }
            }
            const uint32_t* hb = hsm + (kc & 1) * (64 * 68);
#pragma unroll
            for (int ks = 0; ks < 8; ks++) {
                const int k = ks * 8;
                int r = wm * 16 + l4;
                uint32_t a0 = hb[r * 68 + k + tig];
                uint32_t a1 = hb[(r + 8) * 68 + k + tig];
                uint32_t a2 = hb[r * 68 + k + tig + 4];
                uint32_t a3 = hb[(r + 8) * 68 + k + tig + 4];
                int kg = kc * 64 + k;
#pragma unroll
                for (int fn = 0; fn < NF; fn++) {
                    int cc = cbase + fn * 8 + l4;
                    uint32_t b0 = Whs[cc * WST + kg + tig];
                    uint32_t b1 = Whs[cc * WST + kg + tig + 4];
                    mma_tf32(acc[fn], a0, a1, a2, a3, b0, b1);
                }
            }
            if (kc + 1 < NCH) {
                uint32_t* hw = hsm + ((kc + 1) & 1) * (64 * 68);
#pragma unroll
                for (int i = 0; i < 4; i++) {
                    int v = tid + i * 256;
                    uint4 u;
                    u.x = f2tf32(nxt[i].x); u.y = f2tf32(nxt[i].y);
                    u.z = f2tf32(nxt[i].z); u.w = f2tf32(nxt[i].w);
                    *(uint4*)&hw[(v >> 4) * 68 + (v & 15) * 4] = u;
                }
            }
            __syncthreads();
        }

        // dump gate accumulators to SMEM
        {
            int r = wm * 16 + l4;
#pragma unroll
            for (int fn = 0; fn < NF; fn++) {
                int cc = cbase + fn * 8 + 2 * tig;
                gsm[r * GW + cc] = acc[fn][0];
                gsm[r * GW + cc + 1] = acc[fn][1];
                gsm[(r + 8) * GW + cc] = acc[fn][2];
                gsm[(r + 8) * GW + cc + 1] = acc[fn][3];
            }
        }
        __syncthreads();

        // fused LSTM cell on owned hidden units
        for (int e = tid; e < 64 * HW; e += 256) {
            int b = e / HW, u = e % HW;
            const float* Gt = g_G + ((size_t)t * BB + b) * (4 * H);
            float xi = gsm[b * GW + u]          + Gt[j0 + u];
            float xf = gsm[b * GW + HW + u]     + Gt[H + j0 + u];
            float xg = gsm[b * GW + 2 * HW + u] + Gt[2 * H + j0 + u];
            float xo = gsm[b * GW + 3 * HW + u] + Gt[3 * H + j0 + u];
            float cv = sigf(xf) * csm[e] + sigf(xi) * tanhf(xg);
            float hv = sigf(xo) * tanhf(cv);
            csm[e] = cv;
            g_hbuf[cur ^ 1][b * H + j0 + u] = hv;
            if (outSel == 2)
                Hout[((size_t)b * TT + t) * H + j0 + u] = hv;   // (B,T,256) final
            else
                Hout[((size_t)t * BB + b) * H + j0 + u] = hv;   // (T,B,H) sequence
            if (saveFinal && t == TT - 1) {
                g_hT[b * H + j0 + u] = hv;
                g_cT[b * H + j0 + u] = cv;
            }
        }
        grid_sync();
    }
}

// ---------------- host ----------------
static const int SM512 = (32 * 516 + 2 * 64 * 68 + 64 * 32 + 64 * 8) * 4;  // ~111 KB
static const int SM256 = (16 * 260 + 2 * 64 * 68 + 64 * 16 + 64 * 4) * 4;  // ~56 KB

extern "C" void kernel_launch(void* const* d_in, const int* in_sizes, int n_in,
                              void* d_out, int out_size) {
    (void)in_sizes; (void)n_in; (void)out_size;
    const float* x = (const float*)d_in[0];
    const float* p[21];
    for (int i = 0; i < 21; i++) p[i] = (const float*)d_in[i];

    cudaFuncSetAttribute(lstm_rec<512>, cudaFuncAttributeMaxDynamicSharedMemorySize, SM512);
    cudaFuncSetAttribute(lstm_rec<256>, cudaFuncAttributeMaxDynamicSharedMemorySize, SM256);

    dim3 g2048(16, 256), g1024(8, 256);

    // encoder L0: x -> seqA
    gemm_input<<<g2048, 256>>>(0, x, p[1], p[3], p[4], 256, 2048, 0);
    lstm_rec<512><<<64, 256, SM512>>>(p[2], 0, 0, nullptr, 0);
    // encoder L1: seqA -> seqB, save (hT, cT)
    gemm_input<<<g2048, 256>>>(1, x, p[5], p[7], p[8], 512, 2048, 0);
    lstm_rec<512><<<64, 256, SM512>>>(p[6], 0, 1, nullptr, 1);
    // decoder L0: reversed x -> seqA, init from (hT, cT)
    gemm_input<<<g2048, 256>>>(0, x, p[9], p[11], p[12], 256, 2048, 1);
    lstm_rec<512><<<64, 256, SM512>>>(p[10], 1, 0, nullptr, 0);
    // decoder L1: seqA -> seqB
    gemm_input<<<g2048, 256>>>(1, x, p[13], p[15], p[16], 512, 2048, 0);
    lstm_rec<512><<<64, 256, SM512>>>(p[14], 0, 1, nullptr, 0);
    // decoder L2: seqB -> d_out (B,T,256)
    gemm_input<<<g1024, 256>>>(2, x, p[17], p[19], p[20], 512, 1024, 0);
    lstm_rec<256><<<64, 256, SM256>>>(p[18], 0, 2, (float*)d_out, 0);
}

// round 5
// speedup vs baseline: 1.1915x; 1.1915x over previous
#include <cuda_runtime.h>
#include <cstdint>
#include <cstddef>

#define TT 512
#define BB 64
#define NCTA 64

// ---------------- static scratch ----------------
__device__ float g_seqA[(size_t)TT * BB * 512];   // layer-output sequence (T,B,H)
__device__ float g_seqB[(size_t)TT * BB * 512];
__device__ float g_G[(size_t)TT * BB * 2048];     // precomputed input gates (T*B, 4H)
__device__ float g_hbuf[2][BB * 512];             // recurrent h: PERMUTED tf32 fragment layout
__device__ float g_hTp[BB * 512];                 // encoder final h (permuted tf32)
__device__ float g_cT[BB * 512];                  // encoder final c (full precision)
__device__ int g_fl[NCTA];                        // flag barrier
__device__ int g_barCount;
__device__ volatile int g_barGen;

// ---------------- helpers ----------------
__device__ __forceinline__ uint32_t f2tf32(float f) {
    uint32_t u;
    asm("cvt.rna.tf32.f32 %0, %1;" : "=r"(u) : "f"(f));
    return u;
}

__device__ __forceinline__ void mma_tf32(float c[4], uint32_t a0, uint32_t a1,
                                         uint32_t a2, uint32_t a3,
                                         uint32_t b0, uint32_t b1) {
    asm volatile(
        "mma.sync.aligned.m16n8k8.row.col.f32.tf32.tf32.f32 "
        "{%0,%1,%2,%3}, {%4,%5,%6,%7}, {%8,%9}, {%0,%1,%2,%3};"
        : "+f"(c[0]), "+f"(c[1]), "+f"(c[2]), "+f"(c[3])
        : "r"(a0), "r"(a1), "r"(a2), "r"(a3), "r"(b0), "r"(b1));
}

__device__ __forceinline__ float sigf(float x) { return 1.0f / (1.0f + __expf(-x)); }

__device__ __forceinline__ uint32_t smem_u32(const void* p) {
    uint32_t a;
    asm("{ .reg .u64 t; cvta.to.shared.u64 t, %1; cvt.u32.u64 %0, t; }" : "=r"(a) : "l"(p));
    return a;
}

__device__ __forceinline__ void cpa16(uint32_t s, const void* g) {
    asm volatile("cp.async.cg.shared.global [%0], [%1], 16;" :: "r"(s), "l"(g) : "memory");
}
__device__ __forceinline__ void cp_commit() { asm volatile("cp.async.commit_group;" ::: "memory"); }
template <int N>
__device__ __forceinline__ void cp_waitg() { asm volatile("cp.async.wait_group %0;" :: "n"(N) : "memory"); }

// legacy atomic barrier (replay-safe) — used ONCE per launch after init/reset
__device__ __forceinline__ void atomic_bar() {
    __threadfence();
    __syncthreads();
    if (threadIdx.x == 0) {
        int g = g_barGen;
        if (atomicAdd(&g_barCount, 1) == NCTA - 1) {
            g_barCount = 0;
            __threadfence();
            g_barGen = g + 1;
        } else {
            while (g_barGen == g) { __nanosleep(64); }
        }
        __threadfence();
    }
    __syncthreads();
}

// flag-array grid barrier: no atomic serialization. idx = 1,2,... within launch.
// Bounded-spin with nanosleep backoff (the unbounded poll is the prime hang suspect).
__device__ __forceinline__ void fbar(int idx) {
    __syncthreads();
    if (threadIdx.x == 0)
        asm volatile("st.release.gpu.b32 [%0], %1;" :: "l"(&g_fl[blockIdx.x]), "r"(idx) : "memory");
    if (threadIdx.x < NCTA) {
        int v;
        asm volatile("ld.acquire.gpu.b32 %0, [%1];" : "=r"(v) : "l"(&g_fl[threadIdx.x]) : "memory");
        while (v < idx) {
            __nanosleep(32);
            asm volatile("ld.acquire.gpu.b32 %0, [%1];" : "=r"(v) : "l"(&g_fl[threadIdx.x]) : "memory");
        }
    }
    __syncthreads();
}

// ---------------- input GEMM: G = src @ W^T + b1 + b2 --------------------------
__global__ void __launch_bounds__(256) gemm_input(int srcSel,
                                                  const float* __restrict__ xin,
                                                  const float* __restrict__ W,
                                                  const float* __restrict__ b1,
                                                  const float* __restrict__ b2,
                                                  int Kdim, int Ndim, int rev) {
    __shared__ __align__(16) uint32_t As[128][36];
    __shared__ __align__(16) uint32_t Bs[128][36];

    const float* __restrict__ S = (srcSel == 0) ? xin : (srcSel == 1) ? g_seqA : g_seqB;

    int tid = threadIdx.x;
    int wid = tid >> 5, lane = tid & 31, l4 = lane >> 2, tig = lane & 3;
    int wr = wid >> 2, wc = wid & 3;
    int m0 = blockIdx.y * 128, n0 = blockIdx.x * 128;

    float acc[4][4][4];
#pragma unroll
    for (int fm = 0; fm < 4; fm++)
#pragma unroll
        for (int fn = 0; fn < 4; fn++)
#pragma unroll
            for (int i = 0; i < 4; i++) acc[fm][fn][i] = 0.0f;

    for (int kt = 0; kt < Kdim; kt += 32) {
#pragma unroll
        for (int i = 0; i < 4; i++) {
            int v = tid + i * 256;
            int row = v >> 3, kv = v & 7;
            int m = m0 + row;
            size_t off;
            if (srcSel == 0) {
                int t = m >> 6;
                if (rev) t = TT - 1 - t;
                off = ((size_t)(m & 63) * TT + t) * Kdim;
            } else {
                off = (size_t)m * Kdim;
            }
            float4 a4 = *(const float4*)(S + off + kt + kv * 4);
            uint4 ua;
            ua.x = f2tf32(a4.x); ua.y = f2tf32(a4.y);
            ua.z = f2tf32(a4.z); ua.w = f2tf32(a4.w);
            *(uint4*)&As[row][kv * 4] = ua;
            float4 b4 = *(const float4*)(W + (size_t)(n0 + row) * Kdim + kt + kv * 4);
            uint4 ub;
            ub.x = f2tf32(b4.x); ub.y = f2tf32(b4.y);
            ub.z = f2tf32(b4.z); ub.w = f2tf32(b4.w);
            *(uint4*)&Bs[row][kv * 4] = ub;
        }
        __syncthreads();

#pragma unroll
        for (int ks = 0; ks < 4; ks++) {
            const int k = ks * 8;
            uint32_t af[4][4], bf[4][2];
#pragma unroll
            for (int fm = 0; fm < 4; fm++) {
                int r = wr * 64 + fm * 16 + l4;
                af[fm][0] = As[r][k + tig];
                af[fm][1] = As[r + 8][k + tig];
                af[fm][2] = As[r][k + tig + 4];
                af[fm][3] = As[r + 8][k + tig + 4];
            }
#pragma unroll
            for (int fn = 0; fn < 4; fn++) {
                int c = wc * 32 + fn * 8 + l4;
                bf[fn][0] = Bs[c][k + tig];
                bf[fn][1] = Bs[c][k + tig + 4];
            }
#pragma unroll
            for (int fm = 0; fm < 4; fm++)
#pragma unroll
                for (int fn = 0; fn < 4; fn++)
                    mma_tf32(acc[fm][fn], af[fm][0], af[fm][1], af[fm][2], af[fm][3],
                             bf[fn][0], bf[fn][1]);
        }
        __syncthreads();
    }

#pragma unroll
    for (int fm = 0; fm < 4; fm++) {
        int r = m0 + wr * 64 + fm * 16 + l4;
#pragma unroll
        for (int fn = 0; fn < 4; fn++) {
            int c = n0 + wc * 32 + fn * 8 + 2 * tig;
            float bias0 = b1[c] + b2[c];
            float bias1 = b1[c + 1] + b2[c + 1];
            g_G[(size_t)r * Ndim + c]           = acc[fm][fn][0] + bias0;
            g_G[(size_t)r * Ndim + c + 1]       = acc[fm][fn][1] + bias1;
            g_G[(size_t)(r + 8) * Ndim + c]     = acc[fm][fn][2] + bias0;
            g_G[(size_t)(r + 8) * Ndim + c + 1] = acc[fm][fn][3] + bias1;
        }
    }
}

// ---------------- persistent recurrent LSTM pass -------------------------------
// h stored in PERMUTED fragment layout: the mma A-frag is one LDS.128, each
// B-frag one LDS.64. Full h staged to SMEM per step via 2-stage cp.async.
// P(b,k) = (((b>>4)*Kd8 + (k>>3))*32 + (b&7)*4 + (k&3))*4 + ((b>>3)&1) + ((k>>2)&1)*2
template <int H>
__global__ void __launch_bounds__(256) lstm_rec(const float* __restrict__ Whh,
                                                int h0FromEnc, int outSel,
                                                float* __restrict__ outFinal,
                                                int saveFinal) {
    constexpr int HW = H / 64;
    constexpr int GW = 4 * HW;
    constexpr int NF = (GW / 16 > 0) ? GW / 16 : 1;
    constexpr int GWP = GW + 1;
    constexpr int Kd8 = H / 8;
    constexpr int KsPS = Kd8 / 2;          // k-steps per pipeline stage
    constexpr int EPT = (64 * HW) / 256;   // cell elems per thread
    constexpr int NCHK = 4 * KsPS * 32;    // 16B chunks per stage

    extern __shared__ unsigned char smraw[];
    uint32_t* WhsP = (uint32_t*)smraw;               // GW*H u32 (permuted weights)
    uint32_t* hsmP = WhsP + GW * H;                  // 64*H u32 (permuted h)
    float* gsm = (float*)(hsmP + 64 * H);            // 64*GWP
    float* csm = gsm + 64 * GWP;                     // 64*HW

    const int tid = threadIdx.x, bid = blockIdx.x;
    const int wid = tid >> 5, lane = tid & 31, l4 = lane >> 2, tig = lane & 3;
    const int wm = wid & 3, wn = wid >> 2;
    const int j0 = bid * HW;
    const int cbase = wn * (GW / 2);

    float* __restrict__ Hout = (outSel == 0) ? g_seqA : (outSel == 1) ? g_seqB : outFinal;

    // ---- init: permuted Whh slice in SMEM (tf32) ----
    for (int d = tid; d < GW * H; d += 256) {
        int ci = d / (Kd8 * 64);
        int rem = d - ci * (Kd8 * 64);
        int ks = rem >> 6;
        int ln = (rem >> 1) & 31;
        int p = rem & 1;
        int dl4 = ln >> 2, dtig = ln & 3;
        int cc = ci * 8 + dl4;
        int gate = cc / HW, u = cc % HW;
        int k = ks * 8 + dtig + p * 4;
        WhsP[d] = f2tf32(Whh[((size_t)(gate * H + j0 + u)) * H + k]);
    }
    // ---- init: h0 (permuted) and c0 ----
    for (int e = tid; e < 64 * HW; e += 256) {
        int b = e / HW, u = e - b * HW;
        int ug = j0 + u;
        int P = ((((b >> 4) * Kd8 + (ug >> 3)) * 32 + (b & 7) * 4 + (ug & 3)) << 2)
                + ((b >> 3) & 1) + (((ug >> 2) & 1) << 1);
        if (h0FromEnc) {
            csm[e] = g_cT[b * H + ug];
            g_hbuf[0][P] = g_hTp[P];
        } else {
            csm[e] = 0.0f;
            g_hbuf[0][P] = 0.0f;
        }
    }
    if (tid == 0) g_fl[bid] = 0;    // reset flag barrier for this launch / replay
    atomic_bar();                    // replay-safe; makes resets + init visible

    const uint32_t hsm_base = smem_u32(hsmP);

    for (int t = 0; t < TT; t++) {
        const float* __restrict__ hsrc = g_hbuf[t & 1];

        // issue both cp.async stages (k-halves)
#pragma unroll
        for (int s = 0; s < 2; s++) {
            for (int c = tid; c < NCHK; c += 256) {
                int mg = c / (KsPS * 32);
                int rem = c - mg * (KsPS * 32);
                int ksl = rem >> 5;
                int ln = rem & 31;
                int oi = ((mg * Kd8 + s * KsPS + ksl) * 32 + ln) << 2;  // u32 idx
                cpa16(hsm_base + oi * 4, hsrc + oi);
            }
            cp_commit();
        }

        // prefetch G[t] into registers (DRAM latency hides under mma)
        float Gi[EPT], Gf[EPT], Gg[EPT], Go[EPT];
        {
            const float* Gt = g_G + ((size_t)t * BB) * (4 * H);
#pragma unroll
            for (int ei = 0; ei < EPT; ei++) {
                int e = tid + ei * 256;
                int b = e / HW, u = e - b * HW;
                const float* gp = Gt + (size_t)b * (4 * H) + j0 + u;
                Gi[ei] = gp[0]; Gf[ei] = gp[H]; Gg[ei] = gp[2 * H]; Go[ei] = gp[3 * H];
            }
        }

        float acc[NF][4];
#pragma unroll
        for (int fn = 0; fn < NF; fn++)
#pragma unroll
            for (int i = 0; i < 4; i++) acc[fn][i] = 0.0f;

        // ---- stage 0 mma ----
        cp_waitg<1>();
        __syncthreads();
#pragma unroll 4
        for (int ks = 0; ks < KsPS; ks++) {
            uint4 av = *(const uint4*)&hsmP[(((wm * Kd8 + ks) * 32 + lane) << 2)];
#pragma unroll
            for (int fn = 0; fn < NF; fn++) {
                int ci = (cbase >> 3) + fn;
                uint2 bv = *(const uint2*)&WhsP[(ci * Kd8 + ks) * 64 + lane * 2];
                mma_tf32(acc[fn], av.x, av.y, av.z, av.w, bv.x, bv.y);
            }
        }
        // ---- stage 1 mma ----
        cp_waitg<0>();
        __syncthreads();
#pragma unroll 4
        for (int ks = KsPS; ks < 2 * KsPS; ks++) {
            uint4 av = *(const uint4*)&hsmP[(((wm * Kd8 + ks) * 32 + lane) << 2)];
#pragma unroll
            for (int fn = 0; fn < NF; fn++) {
                int ci = (cbase >> 3) + fn;
                uint2 bv = *(const uint2*)&WhsP[(ci * Kd8 + ks) * 64 + lane * 2];
                mma_tf32(acc[fn], av.x, av.y, av.z, av.w, bv.x, bv.y);
            }
        }

        // gate accumulators -> SMEM (warp-exclusive regions)
        {
            int r = wm * 16 + l4;
#pragma unroll
            for (int fn = 0; fn < NF; fn++) {
                int cc = cbase + fn * 8 + 2 * tig;
                gsm[r * GWP + cc]           = acc[fn][0];
                gsm[r * GWP + cc + 1]       = acc[fn][1];
                gsm[(r + 8) * GWP + cc]     = acc[fn][2];
                gsm[(r + 8) * GWP + cc + 1] = acc[fn][3];
            }
        }
        __syncthreads();

        // fused LSTM cell; store h permuted + tf32-rounded
        const int nxt = (t & 1) ^ 1;
#pragma unroll
        for (int ei = 0; ei < EPT; ei++) {
            int e = tid + ei * 256;
            int b = e / HW, u = e - b * HW;
            float xi = gsm[b * GWP + u]          + Gi[ei];
            float xf = gsm[b * GWP + HW + u]     + Gf[ei];
            float xg = gsm[b * GWP + 2 * HW + u] + Gg[ei];
            float xo = gsm[b * GWP + 3 * HW + u] + Go[ei];
            float cv = sigf(xf) * csm[e] + sigf(xi) * tanhf(xg);
            float hv = sigf(xo) * tanhf(cv);
            csm[e] = cv;
            int ug = j0 + u;
            int P = ((((b >> 4) * Kd8 + (ug >> 3)) * 32 + (b & 7) * 4 + (ug & 3)) << 2)
                    + ((b >> 3) & 1) + (((ug >> 2) & 1) << 1);
            float hr = __uint_as_float(f2tf32(hv));
            g_hbuf[nxt][P] = hr;
            if (outSel == 2)
                Hout[((size_t)b * TT + t) * H + ug] = hv;    // (B,T,H) final out
            else
                Hout[((size_t)t * BB + b) * H + ug] = hv;    // (T,B,H) sequence
            if (saveFinal && t == TT - 1) {
                g_hTp[P] = hr;
                g_cT[b * H + ug] = cv;
            }
        }
        fbar(t + 1);
    }
}

// ---------------- host ----------------
static const int SM512 = (32 * 512 + 64 * 512 + 64 * 33 + 64 * 8) * 4;   // 207,104 B
static const int SM256 = (16 * 256 + 64 * 256 + 64 * 17 + 64 * 4) * 4;   //  87,296 B

extern "C" void kernel_launch(void* const* d_in, const int* in_sizes, int n_in,
                              void* d_out, int out_size) {
    (void)in_sizes; (void)n_in; (void)out_size;
    const float* x = (const float*)d_in[0];
    const float* p[21];
    for (int i = 0; i < 21; i++) p[i] = (const float*)d_in[i];

    cudaFuncSetAttribute(lstm_rec<512>, cudaFuncAttributeMaxDynamicSharedMemorySize, SM512);
    cudaFuncSetAttribute(lstm_rec<256>, cudaFuncAttributeMaxDynamicSharedMemorySize, SM256);

    dim3 g2048(16, 256), g1024(8, 256);

    // encoder L0: x -> seqA
    gemm_input<<<g2048, 256>>>(0, x, p[1], p[3], p[4], 256, 2048, 0);
    lstm_rec<512><<<64, 256, SM512>>>(p[2], 0, 0, nullptr, 0);
    // encoder L1: seqA -> seqB, save (hT, cT)
    gemm_input<<<g2048, 256>>>(1, x, p[5], p[7], p[8], 512, 2048, 0);
    lstm_rec<512><<<64, 256, SM512>>>(p[6], 0, 1, nullptr, 1);
    // decoder L0: reversed x -> seqA, init from (hT, cT)
    gemm_input<<<g2048, 256>>>(0, x, p[9], p[11], p[12], 256, 2048, 1);
    lstm_rec<512><<<64, 256, SM512>>>(p[10], 1, 0, nullptr, 0);
    // decoder L1: seqA -> seqB
    gemm_input<<<g2048, 256>>>(1, x, p[13], p[15], p[16], 512, 2048, 0);
    lstm_rec<512><<<64, 256, SM512>>>(p[14], 0, 1, nullptr, 0);
    // decoder L2: seqB -> d_out (B,T,256)
    gemm_input<<<g1024, 256>>>(2, x, p[17], p[19], p[20], 512, 1024, 0);
    lstm_rec<256><<<64, 256, SM256>>>(p[18], 0, 2, (float*)d_out, 0);
}

// round 7
// speedup vs baseline: 1.3117x; 1.1009x over previous
#include <cuda_runtime.h>
#include <cstdint>
#include <cstddef>

#define TT 512
#define BB 64
#define NCTA 64

// ---------------- static scratch ----------------
__device__ float g_seqA[(size_t)TT * BB * 512];   // layer-output sequence (T,B,H)
__device__ float g_seqB[(size_t)TT * BB * 512];
__device__ float g_G[(size_t)TT * BB * 2048];     // precomputed input gates (T*B, 4H)
__device__ float g_hbuf[2][BB * 512];             // recurrent h: PERMUTED tf32 fragment layout
__device__ float g_hTp[BB * 512];                 // encoder final h (permuted tf32)
__device__ float g_cT[BB * 512];                  // encoder final c (full precision)
__device__ int g_fl[NCTA];                        // flag barrier
__device__ int g_barCount;
__device__ volatile int g_barGen;

// ---------------- helpers ----------------
__device__ __forceinline__ uint32_t f2tf32(float f) {
    uint32_t u;
    asm("cvt.rna.tf32.f32 %0, %1;" : "=r"(u) : "f"(f));
    return u;
}

__device__ __forceinline__ void mma_tf32(float c[4], uint32_t a0, uint32_t a1,
                                         uint32_t a2, uint32_t a3,
                                         uint32_t b0, uint32_t b1) {
    asm volatile(
        "mma.sync.aligned.m16n8k8.row.col.f32.tf32.tf32.f32 "
        "{%0,%1,%2,%3}, {%4,%5,%6,%7}, {%8,%9}, {%0,%1,%2,%3};"
        : "+f"(c[0]), "+f"(c[1]), "+f"(c[2]), "+f"(c[3])
        : "r"(a0), "r"(a1), "r"(a2), "r"(a3), "r"(b0), "r"(b1));
}

__device__ __forceinline__ float sigf(float x) { return 1.0f / (1.0f + __expf(-x)); }

__device__ __forceinline__ uint32_t smem_u32(const void* p) {
    uint32_t a;
    asm("{ .reg .u64 t; cvta.to.shared.u64 t, %1; cvt.u32.u64 %0, t; }" : "=r"(a) : "l"(p));
    return a;
}

__device__ __forceinline__ void cpa16(uint32_t s, const void* g) {
    asm volatile("cp.async.cg.shared.global [%0], [%1], 16;" :: "r"(s), "l"(g) : "memory");
}
__device__ __forceinline__ void cp_commit() { asm volatile("cp.async.commit_group;" ::: "memory"); }
template <int N>
__device__ __forceinline__ void cp_waitg() { asm volatile("cp.async.wait_group %0;" :: "n"(N) : "memory"); }

// legacy atomic barrier (replay-safe) — used ONCE per launch after init/reset
__device__ __forceinline__ void atomic_bar() {
    __threadfence();
    __syncthreads();
    if (threadIdx.x == 0) {
        int g = g_barGen;
        if (atomicAdd(&g_barCount, 1) == NCTA - 1) {
            g_barCount = 0;
            __threadfence();
            g_barGen = g + 1;
        } else {
            while (g_barGen == g) { __nanosleep(64); }
        }
        __threadfence();
    }
    __syncthreads();
}

// flag-array grid barrier. idx = 1,2,... within launch.
// RULE (empirical, 5/5 rounds): poll loops on global memory MUST sleep every
// iteration or the container dies. Keep the nanosleep unconditional.
__device__ __forceinline__ void fbar(int idx) {
    __syncthreads();
    if (threadIdx.x == 0)
        asm volatile("st.release.gpu.b32 [%0], %1;" :: "l"(&g_fl[blockIdx.x]), "r"(idx) : "memory");
    if (threadIdx.x < NCTA) {
        int v;
        asm volatile("ld.acquire.gpu.b32 %0, [%1];" : "=r"(v) : "l"(&g_fl[threadIdx.x]) : "memory");
        while (v < idx) {
            __nanosleep(24);
            asm volatile("ld.acquire.gpu.b32 %0, [%1];" : "=r"(v) : "l"(&g_fl[threadIdx.x]) : "memory");
        }
    }
    __syncthreads();
}

// ---------------- input GEMM: G = src @ W^T + b1 + b2 --------------------------
__global__ void __launch_bounds__(256) gemm_input(int srcSel,
                                                  const float* __restrict__ xin,
                                                  const float* __restrict__ W,
                                                  const float* __restrict__ b1,
                                                  const float* __restrict__ b2,
                                                  int Kdim, int Ndim, int rev) {
    __shared__ __align__(16) uint32_t As[128][36];
    __shared__ __align__(16) uint32_t Bs[128][36];

    const float* __restrict__ S = (srcSel == 0) ? xin : (srcSel == 1) ? g_seqA : g_seqB;

    int tid = threadIdx.x;
    int wid = tid >> 5, lane = tid & 31, l4 = lane >> 2, tig = lane & 3;
    int wr = wid >> 2, wc = wid & 3;
    int m0 = blockIdx.y * 128, n0 = blockIdx.x * 128;

    float acc[4][4][4];
#pragma unroll
    for (int fm = 0; fm < 4; fm++)
#pragma unroll
        for (int fn = 0; fn < 4; fn++)
#pragma unroll
            for (int i = 0; i < 4; i++) acc[fm][fn][i] = 0.0f;

    for (int kt = 0; kt < Kdim; kt += 32) {
#pragma unroll
        for (int i = 0; i < 4; i++) {
            int v = tid + i * 256;
            int row = v >> 3, kv = v & 7;
            int m = m0 + row;
            size_t off;
            if (srcSel == 0) {
                int t = m >> 6;
                if (rev) t = TT - 1 - t;
                off = ((size_t)(m & 63) * TT + t) * Kdim;
            } else {
                off = (size_t)m * Kdim;
            }
            float4 a4 = *(const float4*)(S + off + kt + kv * 4);
            uint4 ua;
            ua.x = f2tf32(a4.x); ua.y = f2tf32(a4.y);
            ua.z = f2tf32(a4.z); ua.w = f2tf32(a4.w);
            *(uint4*)&As[row][kv * 4] = ua;
            float4 b4 = *(const float4*)(W + (size_t)(n0 + row) * Kdim + kt + kv * 4);
            uint4 ub;
            ub.x = f2tf32(b4.x); ub.y = f2tf32(b4.y);
            ub.z = f2tf32(b4.z); ub.w = f2tf32(b4.w);
            *(uint4*)&Bs[row][kv * 4] = ub;
        }
        __syncthreads();

#pragma unroll
        for (int ks = 0; ks < 4; ks++) {
            const int k = ks * 8;
            uint32_t af[4][4], bf[4][2];
#pragma unroll
            for (int fm = 0; fm < 4; fm++) {
                int r = wr * 64 + fm * 16 + l4;
                af[fm][0] = As[r][k + tig];
                af[fm][1] = As[r + 8][k + tig];
                af[fm][2] = As[r][k + tig + 4];
                af[fm][3] = As[r + 8][k + tig + 4];
            }
#pragma unroll
            for (int fn = 0; fn < 4; fn++) {
                int c = wc * 32 + fn * 8 + l4;
                bf[fn][0] = Bs[c][k + tig];
                bf[fn][1] = Bs[c][k + tig + 4];
            }
#pragma unroll
            for (int fm = 0; fm < 4; fm++)
#pragma unroll
                for (int fn = 0; fn < 4; fn++)
                    mma_tf32(acc[fm][fn], af[fm][0], af[fm][1], af[fm][2], af[fm][3],
                             bf[fn][0], bf[fn][1]);
        }
        __syncthreads();
    }

#pragma unroll
    for (int fm = 0; fm < 4; fm++) {
        int r = m0 + wr * 64 + fm * 16 + l4;
#pragma unroll
        for (int fn = 0; fn < 4; fn++) {
            int c = n0 + wc * 32 + fn * 8 + 2 * tig;
            float bias0 = b1[c] + b2[c];
            float bias1 = b1[c + 1] + b2[c + 1];
            g_G[(size_t)r * Ndim + c]           = acc[fm][fn][0] + bias0;
            g_G[(size_t)r * Ndim + c + 1]       = acc[fm][fn][1] + bias1;
            g_G[(size_t)(r + 8) * Ndim + c]     = acc[fm][fn][2] + bias0;
            g_G[(size_t)(r + 8) * Ndim + c + 1] = acc[fm][fn][3] + bias1;
        }
    }
}

// ---------------- persistent recurrent LSTM pass -------------------------------
// h in PERMUTED fragment layout: mma A-frag = one LDS.128, B-frag = one LDS.64.
// h staged to SMEM per step via 4-stage cp.async (k-quarters).
// P(b,k) = (((b>>4)*Kd8 + (k>>3))*32 + (b&7)*4 + (k&3))*4 + ((b>>3)&1) + ((k>>2)&1)*2
template <int H>
__global__ void __launch_bounds__(256) lstm_rec(const float* __restrict__ Whh,
                                                int h0FromEnc, int outSel,
                                                float* __restrict__ outFinal,
                                                int saveFinal) {
    constexpr int HW = H / 64;
    constexpr int GW = 4 * HW;
    constexpr int NF = (GW / 16 > 0) ? GW / 16 : 1;
    constexpr int GWP = GW + 1;
    constexpr int Kd8 = H / 8;
    constexpr int NST = 4;                   // pipeline stages
    constexpr int KsPS = Kd8 / NST;          // k-steps per stage
    constexpr int EPT = (64 * HW) / 256;     // cell elems per thread
    constexpr int NCHK = 4 * KsPS * 32;      // 16B chunks per stage

    extern __shared__ unsigned char smraw[];
    uint32_t* WhsP = (uint32_t*)smraw;               // GW*H u32 (permuted weights)
    uint32_t* hsmP = WhsP + GW * H;                  // 64*H u32 (permuted h)
    float* gsm = (float*)(hsmP + 64 * H);            // 64*GWP
    float* csm = gsm + 64 * GWP;                     // 64*HW

    const int tid = threadIdx.x, bid = blockIdx.x;
    const int wid = tid >> 5, lane = tid & 31, l4 = lane >> 2, tig = lane & 3;
    const int wm = wid & 3, wn = wid >> 2;
    const int j0 = bid * HW;
    const int cbase = wn * (GW / 2);

    float* __restrict__ Hout = (outSel == 0) ? g_seqA : (outSel == 1) ? g_seqB : outFinal;

    // ---- init: permuted Whh slice in SMEM (tf32) ----
    for (int d = tid; d < GW * H; d += 256) {
        int ci = d / (Kd8 * 64);
        int rem = d - ci * (Kd8 * 64);
        int ks = rem >> 6;
        int ln = (rem >> 1) & 31;
        int p = rem & 1;
        int dl4 = ln >> 2, dtig = ln & 3;
        int cc = ci * 8 + dl4;
        int gate = cc / HW, u = cc % HW;
        int k = ks * 8 + dtig + p * 4;
        WhsP[d] = f2tf32(Whh[((size_t)(gate * H + j0 + u)) * H + k]);
    }
    // ---- init: h0 (permuted) and c0 ----
    for (int e = tid; e < 64 * HW; e += 256) {
        int b = e / HW, u = e - b * HW;
        int ug = j0 + u;
        int P = ((((b >> 4) * Kd8 + (ug >> 3)) * 32 + (b & 7) * 4 + (ug & 3)) << 2)
                + ((b >> 3) & 1) + (((ug >> 2) & 1) << 1);
        if (h0FromEnc) {
            csm[e] = g_cT[b * H + ug];
            g_hbuf[0][P] = g_hTp[P];
        } else {
            csm[e] = 0.0f;
            g_hbuf[0][P] = 0.0f;
        }
    }
    if (tid == 0) g_fl[bid] = 0;    // reset flag barrier for this launch / replay
    atomic_bar();                    // replay-safe; makes resets + init visible

    const uint32_t hsm_base = smem_u32(hsmP);

    for (int t = 0; t < TT; t++) {
        const float* __restrict__ hsrc = g_hbuf[t & 1];

        // prefetch G[t] into registers FIRST (DRAM latency hides under cp.async + mma)
        float Gi[EPT], Gf[EPT], Gg[EPT], Go[EPT];
        {
            const float* Gt = g_G + ((size_t)t * BB) * (4 * H);
#pragma unroll
            for (int ei = 0; ei < EPT; ei++) {
                int e = tid + ei * 256;
                int b = e / HW, u = e - b * HW;
                const float* gp = Gt + (size_t)b * (4 * H) + j0 + u;
                Gi[ei] = gp[0]; Gf[ei] = gp[H]; Gg[ei] = gp[2 * H]; Go[ei] = gp[3 * H];
            }
        }

        // issue all cp.async stages (k-quarters)
#pragma unroll
        for (int s = 0; s < NST; s++) {
            for (int c = tid; c < NCHK; c += 256) {
                int mg = c / (KsPS * 32);
                int rem = c - mg * (KsPS * 32);
                int ksl = rem >> 5;
                int ln = rem & 31;
                int oi = ((mg * Kd8 + s * KsPS + ksl) * 32 + ln) << 2;  // u32 idx
                cpa16(hsm_base + oi * 4, hsrc + oi);
            }
            cp_commit();
        }

        float acc[NF][4];
#pragma unroll
        for (int fn = 0; fn < NF; fn++)
#pragma unroll
            for (int i = 0; i < 4; i++) acc[fn][i] = 0.0f;

        // ---- staged mma ----
#pragma unroll
        for (int s = 0; s < NST; s++) {
            if (s == 0)      cp_waitg<3>();
            else if (s == 1) cp_waitg<2>();
            else if (s == 2) cp_waitg<1>();
            else             cp_waitg<0>();
            __syncthreads();
#pragma unroll 4
            for (int ks = s * KsPS; ks < (s + 1) * KsPS; ks++) {
                uint4 av = *(const uint4*)&hsmP[(((wm * Kd8 + ks) * 32 + lane) << 2)];
#pragma unroll
                for (int fn = 0; fn < NF; fn++) {
                    int ci = (cbase >> 3) + fn;
                    uint2 bv = *(const uint2*)&WhsP[(ci * Kd8 + ks) * 64 + lane * 2];
                    mma_tf32(acc[fn], av.x, av.y, av.z, av.w, bv.x, bv.y);
                }
            }
        }

        // gate accumulators -> SMEM (warp-exclusive regions)
        {
            int r = wm * 16 + l4;
#pragma unroll
            for (int fn = 0; fn < NF; fn++) {
                int cc = cbase + fn * 8 + 2 * tig;
                gsm[r * GWP + cc]           = acc[fn][0];
                gsm[r * GWP + cc + 1]       = acc[fn][1];
                gsm[(r + 8) * GWP + cc]     = acc[fn][2];
                gsm[(r + 8) * GWP + cc + 1] = acc[fn][3];
            }
        }
        __syncthreads();

        // fused LSTM cell; store h permuted + tf32-rounded
        const int nxt = (t & 1) ^ 1;
#pragma unroll
        for (int ei = 0; ei < EPT; ei++) {
            int e = tid + ei * 256;
            int b = e / HW, u = e - b * HW;
            float xi = gsm[b * GWP + u]          + Gi[ei];
            float xf = gsm[b * GWP + HW + u]     + Gf[ei];
            float xg = gsm[b * GWP + 2 * HW + u] + Gg[ei];
            float xo = gsm[b * GWP + 3 * HW + u] + Go[ei];
            float cv = sigf(xf) * csm[e] + sigf(xi) * tanhf(xg);
            float hv = sigf(xo) * tanhf(cv);
            csm[e] = cv;
            int ug = j0 + u;
            int P = ((((b >> 4) * Kd8 + (ug >> 3)) * 32 + (b & 7) * 4 + (ug & 3)) << 2)
                    + ((b >> 3) & 1) + (((ug >> 2) & 1) << 1);
            float hr = __uint_as_float(f2tf32(hv));
            g_hbuf[nxt][P] = hr;
            if (outSel == 2)
                Hout[((size_t)b * TT + t) * H + ug] = hv;    // (B,T,H) final out
            else
                Hout[((size_t)t * BB + b) * H + ug] = hv;    // (T,B,H) sequence
            if (saveFinal && t == TT - 1) {
                g_hTp[P] = hr;
                g_cT[b * H + ug] = cv;
            }
        }
        fbar(t + 1);
    }
}

// ---------------- host ----------------
static const int SM512 = (32 * 512 + 64 * 512 + 64 * 33 + 64 * 8) * 4;   // 207,104 B
static const int SM256 = (16 * 256 + 64 * 256 + 64 * 17 + 64 * 4) * 4;   //  87,296 B

extern "C" void kernel_launch(void* const* d_in, const int* in_sizes, int n_in,
                              void* d_out, int out_size) {
    (void)in_sizes; (void)n_in; (void)out_size;
    const float* x = (const float*)d_in[0];
    const float* p[21];
    for (int i = 0; i < 21; i++) p[i] = (const float*)d_in[i];

    cudaFuncSetAttribute(lstm_rec<512>, cudaFuncAttributeMaxDynamicSharedMemorySize, SM512);
    cudaFuncSetAttribute(lstm_rec<256>, cudaFuncAttributeMaxDynamicSharedMemorySize, SM256);

    dim3 g2048(16, 256), g1024(8, 256);

    // encoder L0: x -> seqA
    gemm_input<<<g2048, 256>>>(0, x, p[1], p[3], p[4], 256, 2048, 0);
    lstm_rec<512><<<64, 256, SM512>>>(p[2], 0, 0, nullptr, 0);
    // encoder L1: seqA -> seqB, save (hT, cT)
    gemm_input<<<g2048, 256>>>(1, x, p[5], p[7], p[8], 512, 2048, 0);
    lstm_rec<512><<<64, 256, SM512>>>(p[6], 0, 1, nullptr, 1);
    // decoder L0: reversed x -> seqA, init from (hT, cT)
    gemm_input<<<g2048, 256>>>(0, x, p[9], p[11], p[12], 256, 2048, 1);
    lstm_rec<512><<<64, 256, SM512>>>(p[10], 1, 0, nullptr, 0);
    // decoder L1: seqA -> seqB
    gemm_input<<<g2048, 256>>>(1, x, p[13], p[15], p[16], 512, 2048, 0);
    lstm_rec<512><<<64, 256, SM512>>>(p[14], 0, 1, nullptr, 0);
    // decoder L2: seqB -> d_out (B,T,256)
    gemm_input<<<g1024, 256>>>(2, x, p[17], p[19], p[20], 512, 1024, 0);
    lstm_rec<256><<<64, 256, SM256>>>(p[18], 0, 2, (float*)d_out, 0);
}

// round 10
// speedup vs baseline: 1.4549x; 1.1091x over previous
#include <cuda_runtime.h>
#include <cstdint>
#include <cstddef>

#define TT 512
#define BB 64
#define NCTA 64

// ---------------- static scratch ----------------
__device__ float g_seqA[(size_t)TT * BB * 512];   // layer-output sequence (T,B,H)
__device__ float g_seqB[(size_t)TT * BB * 512];
__device__ float g_G[(size_t)TT * BB * 2048];     // precomputed input gates (T*B, 4H)
__device__ float g_hbuf[2][BB * 512];             // recurrent h: PERMUTED tf32 fragment layout
__device__ float g_hTp[BB * 512];                 // encoder final h (permuted tf32)
__device__ float g_cT[BB * 512];                  // encoder final c (full precision)
__device__ int g_fl[NCTA];                        // flag barrier
__device__ int g_barCount;
__device__ volatile int g_barGen;

// ---------------- helpers ----------------
__device__ __forceinline__ uint32_t f2tf32(float f) {
    uint32_t u;
    asm("cvt.rna.tf32.f32 %0, %1;" : "=r"(u) : "f"(f));
    return u;
}

__device__ __forceinline__ void mma_tf32(float c[4], uint32_t a0, uint32_t a1,
                                         uint32_t a2, uint32_t a3,
                                         uint32_t b0, uint32_t b1) {
    asm volatile(
        "mma.sync.aligned.m16n8k8.row.col.f32.tf32.tf32.f32 "
        "{%0,%1,%2,%3}, {%4,%5,%6,%7}, {%8,%9}, {%0,%1,%2,%3};"
        : "+f"(c[0]), "+f"(c[1]), "+f"(c[2]), "+f"(c[3])
        : "r"(a0), "r"(a1), "r"(a2), "r"(a3), "r"(b0), "r"(b1));
}

__device__ __forceinline__ float sigf(float x) { return 1.0f / (1.0f + __expf(-x)); }

__device__ __forceinline__ uint32_t smem_u32(const void* p) {
    uint32_t a;
    asm("{ .reg .u64 t; cvta.to.shared.u64 t, %1; cvt.u32.u64 %0, t; }" : "=r"(a) : "l"(p));
    return a;
}

__device__ __forceinline__ void cpa16(uint32_t s, const void* g) {
    asm volatile("cp.async.cg.shared.global [%0], [%1], 16;" :: "r"(s), "l"(g) : "memory");
}
__device__ __forceinline__ void cp_commit() { asm volatile("cp.async.commit_group;" ::: "memory"); }
template <int N>
__device__ __forceinline__ void cp_waitg() { asm volatile("cp.async.wait_group %0;" :: "n"(N) : "memory"); }

// legacy atomic barrier (replay-safe) — used ONCE per launch after init/reset
__device__ __forceinline__ void atomic_bar() {
    __threadfence();
    __syncthreads();
    if (threadIdx.x == 0) {
        int g = g_barGen;
        if (atomicAdd(&g_barCount, 1) == NCTA - 1) {
            g_barCount = 0;
            __threadfence();
            g_barGen = g + 1;
        } else {
            while (g_barGen == g) { __nanosleep(64); }
        }
        __threadfence();
    }
    __syncthreads();
}

// flag-array grid barrier. idx = 1,2,... within launch.
// Sleep-every-poll; protocol identical to the R7 passing kernel (incl. final step).
__device__ __forceinline__ void fbar(int idx) {
    __syncthreads();
    if (threadIdx.x == 0)
        asm volatile("st.release.gpu.b32 [%0], %1;" :: "l"(&g_fl[blockIdx.x]), "r"(idx) : "memory");
    if (threadIdx.x < NCTA) {
        int v;
        asm volatile("ld.acquire.gpu.b32 %0, [%1];" : "=r"(v) : "l"(&g_fl[threadIdx.x]) : "memory");
        while (v < idx) {
            __nanosleep(24);
            asm volatile("ld.acquire.gpu.b32 %0, [%1];" : "=r"(v) : "l"(&g_fl[threadIdx.x]) : "memory");
        }
    }
    __syncthreads();
}

// ---------------- input GEMM: G = src @ W^T + b1 + b2 --------------------------
// Register double-buffered: prefetch next K-tile to regs while mma-ing current
// SMEM tile; STS after all reads. Hides the LDG latency that was serial before.
__global__ void __launch_bounds__(256) gemm_input(int srcSel,
                                                  const float* __restrict__ xin,
                                                  const float* __restrict__ W,
                                                  const float* __restrict__ b1,
                                                  const float* __restrict__ b2,
                                                  int Kdim, int Ndim, int rev) {
    __shared__ __align__(16) uint32_t As[128][36];
    __shared__ __align__(16) uint32_t Bs[128][36];

    const float* __restrict__ S = (srcSel == 0) ? xin : (srcSel == 1) ? g_seqA : g_seqB;

    int tid = threadIdx.x;
    int wid = tid >> 5, lane = tid & 31, l4 = lane >> 2, tig = lane & 3;
    int wr = wid >> 2, wc = wid & 3;
    int m0 = blockIdx.y * 128, n0 = blockIdx.x * 128;

    // per-thread source offsets for the 4 (row, kv) slots this thread fills
    size_t aoff[4];
    const float* wrow[4];
#pragma unroll
    for (int i = 0; i < 4; i++) {
        int v = tid + i * 256;
        int row = v >> 3, kv = v & 7;
        int m = m0 + row;
        size_t off;
        if (srcSel == 0) {
            int t = m >> 6;
            if (rev) t = TT - 1 - t;
            off = ((size_t)(m & 63) * TT + t) * Kdim;
        } else {
            off = (size_t)m * Kdim;
        }
        aoff[i] = off + kv * 4;
        wrow[i] = W + (size_t)(n0 + row) * Kdim + kv * 4;
    }

    float acc[4][4][4];
#pragma unroll
    for (int fm = 0; fm < 4; fm++)
#pragma unroll
        for (int fn = 0; fn < 4; fn++)
#pragma unroll
            for (int i = 0; i < 4; i++) acc[fm][fn][i] = 0.0f;

    // prologue: load tile 0 into regs
    float4 ra[4], rb[4];
#pragma unroll
    for (int i = 0; i < 4; i++) {
        ra[i] = *(const float4*)(S + aoff[i]);
        rb[i] = *(const float4*)(wrow[i]);
    }

    for (int kt = 0; kt < Kdim; kt += 32) {
        // store current regs to SMEM (tf32-rounded, identical numerics to before)
#pragma unroll
        for (int i = 0; i < 4; i++) {
            int v = tid + i * 256;
            int row = v >> 3, kv = v & 7;
            uint4 ua, ub;
            ua.x = f2tf32(ra[i].x); ua.y = f2tf32(ra[i].y);
            ua.z = f2tf32(ra[i].z); ua.w = f2tf32(ra[i].w);
            ub.x = f2tf32(rb[i].x); ub.y = f2tf32(rb[i].y);
            ub.z = f2tf32(rb[i].z); ub.w = f2tf32(rb[i].w);
            *(uint4*)&As[row][kv * 4] = ua;
            *(uint4*)&Bs[row][kv * 4] = ub;
        }
        __syncthreads();

        // prefetch next tile into regs (overlaps with mma below)
        if (kt + 32 < Kdim) {
#pragma unroll
            for (int i = 0; i < 4; i++) {
                ra[i] = *(const float4*)(S + aoff[i] + kt + 32);
                rb[i] = *(const float4*)(wrow[i] + kt + 32);
            }
        }

#pragma unroll
        for (int ks = 0; ks < 4; ks++) {
            const int k = ks * 8;
            uint32_t af[4][4], bf[4][2];
#pragma unroll
            for (int fm = 0; fm < 4; fm++) {
                int r = wr * 64 + fm * 16 + l4;
                af[fm][0] = As[r][k + tig];
                af[fm][1] = As[r + 8][k + tig];
                af[fm][2] = As[r][k + tig + 4];
                af[fm][3] = As[r + 8][k + tig + 4];
            }
#pragma unroll
            for (int fn = 0; fn < 4; fn++) {
                int c = wc * 32 + fn * 8 + l4;
                bf[fn][0] = Bs[c][k + tig];
                bf[fn][1] = Bs[c][k + tig + 4];
            }
#pragma unroll
            for (int fm = 0; fm < 4; fm++)
#pragma unroll
                for (int fn = 0; fn < 4; fn++)
                    mma_tf32(acc[fm][fn], af[fm][0], af[fm][1], af[fm][2], af[fm][3],
                             bf[fn][0], bf[fn][1]);
        }
        __syncthreads();
    }

#pragma unroll
    for (int fm = 0; fm < 4; fm++) {
        int r = m0 + wr * 64 + fm * 16 + l4;
#pragma unroll
        for (int fn = 0; fn < 4; fn++) {
            int c = n0 + wc * 32 + fn * 8 + 2 * tig;
            float bias0 = b1[c] + b2[c];
            float bias1 = b1[c + 1] + b2[c + 1];
            g_G[(size_t)r * Ndim + c]           = acc[fm][fn][0] + bias0;
            g_G[(size_t)r * Ndim + c + 1]       = acc[fm][fn][1] + bias1;
            g_G[(size_t)(r + 8) * Ndim + c]     = acc[fm][fn][2] + bias0;
            g_G[(size_t)(r + 8) * Ndim + c + 1] = acc[fm][fn][3] + bias1;
        }
    }
}

// ---------------- persistent recurrent LSTM pass -------------------------------
// h in PERMUTED fragment layout: mma A-frag = one LDS.128, B-frag = one LDS.64.
// h staged to SMEM per step via 4-stage cp.async (k-quarters).
// 2 accumulator banks per fn (ks parity) break the HMMA RAW chain.
// P(b,k) = (((b>>4)*Kd8 + (k>>3))*32 + (b&7)*4 + (k&3))*4 + ((b>>3)&1) + ((k>>2)&1)*2
template <int H>
__global__ void __launch_bounds__(256, 1) lstm_rec(const float* __restrict__ Whh,
                                                   int h0FromEnc, int outSel,
                                                   float* __restrict__ outFinal,
                                                   int saveFinal) {
    constexpr int HW = H / 64;
    constexpr int GW = 4 * HW;
    constexpr int NF = (GW / 16 > 0) ? GW / 16 : 1;
    constexpr int GWP = GW + 1;
    constexpr int Kd8 = H / 8;
    constexpr int NST = 4;                   // pipeline stages
    constexpr int KsPS = Kd8 / NST;          // k-steps per stage
    constexpr int EPT = (64 * HW) / 256;     // cell elems per thread
    constexpr int NCHK = 4 * KsPS * 32;      // 16B chunks per stage

    extern __shared__ unsigned char smraw[];
    uint32_t* WhsP = (uint32_t*)smraw;               // GW*H u32 (permuted weights)
    uint32_t* hsmP = WhsP + GW * H;                  // 64*H u32 (permuted h)
    float* gsm = (float*)(hsmP + 64 * H);            // 64*GWP
    float* csm = gsm + 64 * GWP;                     // 64*HW

    const int tid = threadIdx.x, bid = blockIdx.x;
    const int wid = tid >> 5, lane = tid & 31, l4 = lane >> 2, tig = lane & 3;
    const int wm = wid & 3, wn = wid >> 2;
    const int j0 = bid * HW;
    const int cbase = wn * (GW / 2);

    float* __restrict__ Hout = (outSel == 0) ? g_seqA : (outSel == 1) ? g_seqB : outFinal;

    // ---- init: permuted Whh slice in SMEM (tf32) ----
    for (int d = tid; d < GW * H; d += 256) {
        int ci = d / (Kd8 * 64);
        int rem = d - ci * (Kd8 * 64);
        int ks = rem >> 6;
        int ln = (rem >> 1) & 31;
        int p = rem & 1;
        int dl4 = ln >> 2, dtig = ln & 3;
        int cc = ci * 8 + dl4;
        int gate = cc / HW, u = cc % HW;
        int k = ks * 8 + dtig + p * 4;
        WhsP[d] = f2tf32(Whh[((size_t)(gate * H + j0 + u)) * H + k]);
    }
    // ---- init: h0 (permuted) and c0 ----
    for (int e = tid; e < 64 * HW; e += 256) {
        int b = e / HW, u = e - b * HW;
        int ug = j0 + u;
        int P = ((((b >> 4) * Kd8 + (ug >> 3)) * 32 + (b & 7) * 4 + (ug & 3)) << 2)
                + ((b >> 3) & 1) + (((ug >> 2) & 1) << 1);
        if (h0FromEnc) {
            csm[e] = g_cT[b * H + ug];
            g_hbuf[0][P] = g_hTp[P];
        } else {
            csm[e] = 0.0f;
            g_hbuf[0][P] = 0.0f;
        }
    }
    if (tid == 0) g_fl[bid] = 0;    // reset flag barrier for this launch / replay
    atomic_bar();                    // replay-safe; makes resets + init visible

    const uint32_t hsm_base = smem_u32(hsmP);

    for (int t = 0; t < TT; t++) {
        const float* __restrict__ hsrc = g_hbuf[t & 1];

        // prefetch G[t] into registers FIRST (DRAM latency hides under cp.async + mma)
        float Gi[EPT], Gf[EPT], Gg[EPT], Go[EPT];
        {
            const float* Gt = g_G + ((size_t)t * BB) * (4 * H);
#pragma unroll
            for (int ei = 0; ei < EPT; ei++) {
                int e = tid + ei * 256;
                int b = e / HW, u = e - b * HW;
                const float* gp = Gt + (size_t)b * (4 * H) + j0 + u;
                Gi[ei] = gp[0]; Gf[ei] = gp[H]; Gg[ei] = gp[2 * H]; Go[ei] = gp[3 * H];
            }
        }

        // issue all cp.async stages (k-quarters)
#pragma unroll
        for (int s = 0; s < NST; s++) {
            for (int c = tid; c < NCHK; c += 256) {
                int mg = c / (KsPS * 32);
                int rem = c - mg * (KsPS * 32);
                int ksl = rem >> 5;
                int ln = rem & 31;
                int oi = ((mg * Kd8 + s * KsPS + ksl) * 32 + ln) << 2;  // u32 idx
                cpa16(hsm_base + oi * 4, hsrc + oi);
            }
            cp_commit();
        }

        // 2 accumulator banks per fn — breaks the HMMA RAW chain
        float acc[NF][2][4];
#pragma unroll
        for (int fn = 0; fn < NF; fn++)
#pragma unroll
            for (int bk = 0; bk < 2; bk++)
#pragma unroll
                for (int i = 0; i < 4; i++) acc[fn][bk][i] = 0.0f;

        // ---- staged mma ----
#pragma unroll
        for (int s = 0; s < NST; s++) {
            if (s == 0)      cp_waitg<3>();
            else if (s == 1) cp_waitg<2>();
            else if (s == 2) cp_waitg<1>();
            else             cp_waitg<0>();
            __syncthreads();
#pragma unroll 4
            for (int ks = s * KsPS; ks < (s + 1) * KsPS; ks++) {
                uint4 av = *(const uint4*)&hsmP[(((wm * Kd8 + ks) * 32 + lane) << 2)];
                const int bk = ks & 1;
#pragma unroll
                for (int fn = 0; fn < NF; fn++) {
                    int ci = (cbase >> 3) + fn;
                    uint2 bv = *(const uint2*)&WhsP[(ci * Kd8 + ks) * 64 + lane * 2];
                    mma_tf32(acc[fn][bk], av.x, av.y, av.z, av.w, bv.x, bv.y);
                }
            }
        }

        // gate accumulators (banks merged) -> SMEM (warp-exclusive regions)
        {
            int r = wm * 16 + l4;
#pragma unroll
            for (int fn = 0; fn < NF; fn++) {
                int cc = cbase + fn * 8 + 2 * tig;
                gsm[r * GWP + cc]           = acc[fn][0][0] + acc[fn][1][0];
                gsm[r * GWP + cc + 1]       = acc[fn][0][1] + acc[fn][1][1];
                gsm[(r + 8) * GWP + cc]     = acc[fn][0][2] + acc[fn][1][2];
                gsm[(r + 8) * GWP + cc + 1] = acc[fn][0][3] + acc[fn][1][3];
            }
        }
        __syncthreads();

        // fused LSTM cell; store h permuted + tf32-rounded
        const int nxt = (t & 1) ^ 1;
#pragma unroll
        for (int ei = 0; ei < EPT; ei++) {
            int e = tid + ei * 256;
            int b = e / HW, u = e - b * HW;
            float xi = gsm[b * GWP + u]          + Gi[ei];
            float xf = gsm[b * GWP + HW + u]     + Gf[ei];
            float xg = gsm[b * GWP + 2 * HW + u] + Gg[ei];
            float xo = gsm[b * GWP + 3 * HW + u] + Go[ei];
            float cv = sigf(xf) * csm[e] + sigf(xi) * tanhf(xg);
            float hv = sigf(xo) * tanhf(cv);
            csm[e] = cv;
            int ug = j0 + u;
            int P = ((((b >> 4) * Kd8 + (ug >> 3)) * 32 + (b & 7) * 4 + (ug & 3)) << 2)
                    + ((b >> 3) & 1) + (((ug >> 2) & 1) << 1);
            float hr = __uint_as_float(f2tf32(hv));
            g_hbuf[nxt][P] = hr;
            if (outSel == 2)
                Hout[((size_t)b * TT + t) * H + ug] = hv;    // (B,T,H) final out
            else
                Hout[((size_t)t * BB + b) * H + ug] = hv;    // (T,B,H) sequence
            if (saveFinal && t == TT - 1) {
                g_hTp[P] = hr;
                g_cT[b * H + ug] = cv;
            }
        }
        fbar(t + 1);
    }
}

// ---------------- host ----------------
static const int SM512 = (32 * 512 + 64 * 512 + 64 * 33 + 64 * 8) * 4;   // 207,104 B
static const int SM256 = (16 * 256 + 64 * 256 + 64 * 17 + 64 * 4) * 4;   //  87,296 B

extern "C" void kernel_launch(void* const* d_in, const int* in_sizes, int n_in,
                              void* d_out, int out_size) {
    (void)in_sizes; (void)n_in; (void)out_size;
    const float* x = (const float*)d_in[0];
    const float* p[21];
    for (int i = 0; i < 21; i++) p[i] = (const float*)d_in[i];

    cudaFuncSetAttribute(lstm_rec<512>, cudaFuncAttributeMaxDynamicSharedMemorySize, SM512);
    cudaFuncSetAttribute(lstm_rec<256>, cudaFuncAttributeMaxDynamicSharedMemorySize, SM256);

    dim3 g2048(16, 256), g1024(8, 256);

    // encoder L0: x -> seqA
    gemm_input<<<g2048, 256>>>(0, x, p[1], p[3], p[4], 256, 2048, 0);
    lstm_rec<512><<<64, 256, SM512>>>(p[2], 0, 0, nullptr, 0);
    // encoder L1: seqA -> seqB, save (hT, cT)
    gemm_input<<<g2048, 256>>>(1, x, p[5], p[7], p[8], 512, 2048, 0);
    lstm_rec<512><<<64, 256, SM512>>>(p[6], 0, 1, nullptr, 1);
    // decoder L0: reversed x -> seqA, init from (hT, cT)
    gemm_input<<<g2048, 256>>>(0, x, p[9], p[11], p[12], 256, 2048, 1);
    lstm_rec<512><<<64, 256, SM512>>>(p[10], 1, 0, nullptr, 0);
    // decoder L1: seqA -> seqB
    gemm_input<<<g2048, 256>>>(1, x, p[13], p[15], p[16], 512, 2048, 0);
    lstm_rec<512><<<64, 256, SM512>>>(p[14], 0, 1, nullptr, 0);
    // decoder L2: seqB -> d_out (B,T,256)
    gemm_input<<<g1024, 256>>>(2, x, p[17], p[19], p[20], 512, 1024, 0);
    lstm_rec<256><<<64, 256, SM256>>>(p[18], 0, 2, (float*)d_out, 0);
}